// round 14
// baseline (speedup 1.0000x reference)
#include <cuda_runtime.h>
#include <cuda_bf16.h>
#include <cstdint>

// Problem constants
#define T_LEN   32768
#define IN_DIM  1024
#define HSZ     20
#define NG      80      // 4*H gates
#define NLAYER  4
#define U       8                 // timesteps per block-tick
#define NB      (T_LEN / U)       // 4096 blocks
#define NT      (NB + 7)          // total ticks (pipeline offset 2/layer + 1)

// Scratch: precomputed layer-0 input projection (+ both layer-0 biases),
// interleaved: proj[t*80 + unit*4 + cls], cls = {i,f,g,o}
__device__ float g_proj[T_LEN * NG];   // 10.5 MB

// ---------------------------------------------------------------------------
// Kernel 1: proj[t][u][c] = sum_i x[t][i] * W_ih0[c*20+u][i] + b_ih0 + b_hh0
// ---------------------------------------------------------------------------
#define TILE_T 8

__global__ void __launch_bounds__(320) proj_kernel(
    const float* __restrict__ x,
    const float* __restrict__ W_ih0,
    const float* __restrict__ b_ih0,
    const float* __restrict__ b_hh0,
    float* __restrict__ proj)
{
    __shared__ __align__(16) float xs[TILE_T * IN_DIM];

    const int t0 = blockIdx.x * TILE_T;

    const float4* xg  = (const float4*)(x + (size_t)t0 * IN_DIM);
    float4*       xs4 = (float4*)xs;
    for (int i = threadIdx.x; i < TILE_T * (IN_DIM / 4); i += blockDim.x)
        xs4[i] = xg[i];
    __syncthreads();

    const int g  = threadIdx.x % NG;   // gate row 0..79
    const int tg = threadIdx.x / NG;   // 0..3, each handles 2 timesteps

    float acc0 = 0.f, acc1 = 0.f;
    const float4* Wg = (const float4*)(W_ih0 + (size_t)g * IN_DIM);
    const float4* xa = (const float4*)(xs + (tg * 2 + 0) * IN_DIM);
    const float4* xb = (const float4*)(xs + (tg * 2 + 1) * IN_DIM);

    #pragma unroll 8
    for (int k = 0; k < IN_DIM / 4; k++) {
        float4 w = __ldg(&Wg[k]);
        float4 a = xa[k];
        float4 b = xb[k];
        acc0 = fmaf(w.x, a.x, acc0); acc0 = fmaf(w.y, a.y, acc0);
        acc0 = fmaf(w.z, a.z, acc0); acc0 = fmaf(w.w, a.w, acc0);
        acc1 = fmaf(w.x, b.x, acc1); acc1 = fmaf(w.y, b.y, acc1);
        acc1 = fmaf(w.z, b.z, acc1); acc1 = fmaf(w.w, b.w, acc1);
    }

    const float bias = b_ih0[g] + b_hh0[g];
    const int   unit = g % HSZ;
    const int   cls  = g / HSZ;
    proj[(size_t)(t0 + tg * 2 + 0) * NG + unit * 4 + cls] = acc0 + bias;
    proj[(size_t)(t0 + tg * 2 + 1) * NG + unit * 4 + cls] = acc1 + bias;
}

// ---------------------------------------------------------------------------
// Packed f32x2 helpers (FFMA2 — PTX-only on sm_103a)
// ---------------------------------------------------------------------------
__device__ __forceinline__ uint64_t pack2(float lo, float hi) {
    uint64_t r;
    asm("mov.b64 %0, {%1, %2};" : "=l"(r) : "f"(lo), "f"(hi));
    return r;
}
__device__ __forceinline__ void unpack2(uint64_t v, float& lo, float& hi) {
    asm("mov.b64 {%0, %1}, %2;" : "=f"(lo), "=f"(hi) : "l"(v));
}
__device__ __forceinline__ void fma2(uint64_t& d, uint64_t a, uint64_t b) {
    asm("fma.rn.f32x2 %0, %1, %2, %3;" : "=l"(d) : "l"(a), "l"(b), "l"(d));
}
__device__ __forceinline__ float tanh_fast(float x) {
    float y;
    asm("tanh.approx.f32 %0, %1;" : "=f"(y) : "f"(x));
    return y;
}
__device__ __forceinline__ float sig_fast(float x) {
    return fmaf(0.5f, tanh_fast(0.5f * x), 0.5f);
}
// sum of the two packed halves
__device__ __forceinline__ float hsum2(uint64_t v) {
    float lo, hi; unpack2(v, lo, hi); return lo + hi;
}

// ---------------------------------------------------------------------------
// Kernel 2: single-CTA block-wavefront LSTM, 256 threads = 8 warps.
// WARP-PRIORITY LAYOUT (arbiter is highest-wid-first on B300):
//   warp 0..2 : input-term helper for layer wid+1 (latency-tolerant, LOW prio)
//   warp 3    : layer-0 projection stager from gmem (most tolerant, low prio)
//   warp 4..7 : recurrence warp for layer wid-4 (serial critical path,
//               HIGH priority; one per SMSP). Lane j owns unit j.
// Tick n: rec warp L runs block b = n-1-2L (8 steps, warp-internal only);
// helper l produces pin for block n-2l. ONE __syncthreads per tick.
// Hazards: all producers write parity p=n&1, all consumers read p^1; a
// buffer written at tick n is only read at tick n+1.
// ---------------------------------------------------------------------------
__global__ void __launch_bounds__(256, 1) lstm_seq_kernel(
    const float* __restrict__ W_hh0,
    const float* __restrict__ W_ih_r,
    const float* __restrict__ W_hh_r,
    const float* __restrict__ b_ih_r,
    const float* __restrict__ b_hh_r,
    const float* __restrict__ lin_w,
    const float* __restrict__ lin_b,
    const float* __restrict__ proj,
    float* __restrict__ out)
{
    // h_sh[parity][layer][step][unit]
    __shared__ __align__(16) float h_sh[2][NLAYER][U][HSZ];
    // pin_sh[parity][layer][step][unit][gate]
    __shared__ __align__(16) float pin_sh[2][NLAYER][U][HSZ][4];

    const int tid  = threadIdx.x;
    const int wid  = tid >> 5;
    const int lane = tid & 31;
    const bool own = (lane < HSZ);

    // zero shared h state
    for (int i = tid; i < 2 * NLAYER * U * HSZ; i += blockDim.x)
        ((float*)h_sh)[i] = 0.f;
    __syncthreads();

    if (wid >= 4) {
        // ---------------- recurrence warp, layer L (HIGH wid = HIGH prio) ---
        const int L = wid - 4;
        uint64_t whh2[4][10];
        if (own) {
            #pragma unroll
            for (int c = 0; c < 4; c++) {
                const float* row = (L == 0)
                    ? (W_hh0 + (c * HSZ + lane) * HSZ)
                    : (W_hh_r + (L - 1) * NG * HSZ + (c * HSZ + lane) * HSZ);
                #pragma unroll
                for (int q = 0; q < 10; q++)
                    whh2[c][q] = pack2(row[2 * q], row[2 * q + 1]);
            }
        }
        float c_state = 0.f;

        for (int n = 0; n < NT; n++) {
            const int b = n - 1 - 2 * L;
            if (own && b >= 0 && b < NB) {
                const int p = n & 1;
                const float* pin_src = &pin_sh[p ^ 1][L][0][lane][0];
                float*       hw      = &h_sh[p][L][0][0];
                const float* z_prev  = &h_sh[p ^ 1][L][U - 1][0];

                #pragma unroll
                for (int s = 0; s < U; s++) {
                    const float* zs = (s == 0) ? z_prev : (hw + (s - 1) * HSZ);
                    uint64_t z[10];
                    {
                        const ulonglong2* zp = (const ulonglong2*)zs;
                        #pragma unroll
                        for (int q = 0; q < 5; q++) {
                            ulonglong2 v = zp[q];
                            z[2 * q] = v.x; z[2 * q + 1] = v.y;
                        }
                    }
                    const float4 pv = *(const float4*)(pin_src + s * (HSZ * 4));
                    // two 5-deep partial chains per gate (shorter dep tail)
                    uint64_t a0 = pack2(pv.x, 0.f), e0 = 0ull;
                    uint64_t a1 = pack2(pv.y, 0.f), e1 = 0ull;
                    uint64_t a2 = pack2(pv.z, 0.f), e2 = 0ull;
                    uint64_t a3 = pack2(pv.w, 0.f), e3 = 0ull;
                    #pragma unroll
                    for (int q = 0; q < 5; q++) {
                        fma2(a0, whh2[0][q], z[q]);
                        fma2(a1, whh2[1][q], z[q]);
                        fma2(a2, whh2[2][q], z[q]);
                        fma2(a3, whh2[3][q], z[q]);
                        fma2(e0, whh2[0][q + 5], z[q + 5]);
                        fma2(e1, whh2[1][q + 5], z[q + 5]);
                        fma2(e2, whh2[2][q + 5], z[q + 5]);
                        fma2(e3, whh2[3][q + 5], z[q + 5]);
                    }
                    const float gi = hsum2(a0) + hsum2(e0);
                    const float gf = hsum2(a1) + hsum2(e1);
                    const float gg = hsum2(a2) + hsum2(e2);
                    const float go = hsum2(a3) + hsum2(e3);

                    const float si = sig_fast(gi);
                    const float sf = sig_fast(gf);
                    const float tg = tanh_fast(gg);
                    const float so = sig_fast(go);
                    c_state = fmaf(sf, c_state, si * tg);
                    hw[s * HSZ + lane] = so * tanh_fast(c_state);
                    __syncwarp(0x000FFFFFu);
                }
            }
            __syncthreads();
        }
    } else if (wid < 3) {
        // ---------------- input-term helper, layer l = wid+1 (low prio) ----
        const int l = wid + 1;            // 1..3
        uint64_t wih2[4][10];
        float4   bias4 = make_float4(0.f, 0.f, 0.f, 0.f);
        if (own) {
            const int lbase = (l - 1) * NG * HSZ;
            #pragma unroll
            for (int c = 0; c < 4; c++) {
                const float* ri = W_ih_r + lbase + (c * HSZ + lane) * HSZ;
                #pragma unroll
                for (int q = 0; q < 10; q++)
                    wih2[c][q] = pack2(ri[2 * q], ri[2 * q + 1]);
            }
            const int bo = (l - 1) * NG + lane;
            bias4.x = b_ih_r[bo]           + b_hh_r[bo];
            bias4.y = b_ih_r[bo + HSZ]     + b_hh_r[bo + HSZ];
            bias4.z = b_ih_r[bo + 2 * HSZ] + b_hh_r[bo + 2 * HSZ];
            bias4.w = b_ih_r[bo + 3 * HSZ] + b_hh_r[bo + 3 * HSZ];
        }

        for (int n = 0; n < NT; n++) {
            const int b = n - 2 * l;
            if (own && b >= 0 && b < NB) {
                const int p = n & 1;
                const float* hsrc = &h_sh[p ^ 1][l - 1][0][0];
                float*       pw   = &pin_sh[p][l][0][lane][0];

                #pragma unroll
                for (int s = 0; s < U; s++) {
                    uint64_t z[10];
                    {
                        const ulonglong2* zp =
                            (const ulonglong2*)(hsrc + s * HSZ);
                        #pragma unroll
                        for (int q = 0; q < 5; q++) {
                            ulonglong2 v = zp[q];
                            z[2 * q] = v.x; z[2 * q + 1] = v.y;
                        }
                    }
                    uint64_t a0 = pack2(bias4.x, 0.f);
                    uint64_t a1 = pack2(bias4.y, 0.f);
                    uint64_t a2 = pack2(bias4.z, 0.f);
                    uint64_t a3 = pack2(bias4.w, 0.f);
                    #pragma unroll
                    for (int q = 0; q < 10; q++) {
                        fma2(a0, wih2[0][q], z[q]);
                        fma2(a1, wih2[1][q], z[q]);
                        fma2(a2, wih2[2][q], z[q]);
                        fma2(a3, wih2[3][q], z[q]);
                    }
                    float4 r;
                    r.x = hsum2(a0);
                    r.y = hsum2(a1);
                    r.z = hsum2(a2);
                    r.w = hsum2(a3);
                    *(float4*)(pw + s * (HSZ * 4)) = r;
                }
            }
            __syncthreads();
        }
    } else {
        // ---------------- layer-0 projection stager (warp 3, low prio) -----
        const float4* proj4 = (const float4*)proj;
        for (int n = 0; n < NT; n++) {
            const int b = n;
            if (own && b < NB) {
                const int p = n & 1;
                float4* pw = (float4*)&pin_sh[p][0][0][lane][0];
                #pragma unroll
                for (int s = 0; s < U; s++)
                    pw[s * HSZ] =
                        __ldg(&proj4[(size_t)(b * U + s) * HSZ + lane]);
            }
            __syncthreads();
        }
    }

    __syncthreads();

    // Final linear + sigmoid on h^{L-1}_{T-1}
    if (tid == 0) {
        const int pLast = (NT - 1) & 1;
        float acc = lin_b[0];
        #pragma unroll
        for (int k = 0; k < HSZ; k++)
            acc = fmaf(h_sh[pLast][NLAYER - 1][U - 1][k], lin_w[k], acc);
        out[0] = 1.0f / (1.0f + __expf(-acc));
    }
}

// ---------------------------------------------------------------------------
// Launch
// ---------------------------------------------------------------------------
extern "C" void kernel_launch(void* const* d_in, const int* in_sizes, int n_in,
                              void* d_out, int out_size)
{
    const float* x      = (const float*)d_in[0];
    const float* W_ih0  = (const float*)d_in[1];
    const float* W_hh0  = (const float*)d_in[2];
    const float* b_ih0  = (const float*)d_in[3];
    const float* b_hh0  = (const float*)d_in[4];
    const float* W_ih_r = (const float*)d_in[5];
    const float* W_hh_r = (const float*)d_in[6];
    const float* b_ih_r = (const float*)d_in[7];
    const float* b_hh_r = (const float*)d_in[8];
    const float* lin_w  = (const float*)d_in[9];
    const float* lin_b  = (const float*)d_in[10];
    float* out = (float*)d_out;

    float* proj;
    cudaGetSymbolAddress((void**)&proj, g_proj);

    proj_kernel<<<T_LEN / TILE_T, 320>>>(x, W_ih0, b_ih0, b_hh0, proj);
    lstm_seq_kernel<<<1, 256>>>(W_hh0, W_ih_r, W_hh_r, b_ih_r, b_hh_r,
                                lin_w, lin_b, proj, out);
}

// round 17
// speedup vs baseline: 1.0461x; 1.0461x over previous
#include <cuda_runtime.h>
#include <cuda_bf16.h>
#include <cstdint>

// Problem constants
#define T_LEN   32768
#define IN_DIM  1024
#define HSZ     20
#define NG      80      // 4*H gates
#define NLAYER  4
#define U       8                 // timesteps per block-tick
#define NB      (T_LEN / U)       // 4096 blocks
#define NT      (NB + 7)          // total ticks (pipeline offset 2/layer + 1)

// Scratch: precomputed layer-0 input projection (+ both layer-0 biases),
// interleaved: proj[t*80 + unit*4 + cls], cls = {i,f,g,o}.
// NOTE: i,f,o entries are PRE-SCALED by 0.5 (sigmoid = 0.5*tanh(x/2)+0.5).
__device__ float g_proj[T_LEN * NG];   // 10.5 MB

// ---------------------------------------------------------------------------
// Kernel 1: proj[t][u][c] = (sum_i x[t][i]*W_ih0[c*20+u][i] + b_ih0 + b_hh0)
//                            * (c==g ? 1 : 0.5)
// ---------------------------------------------------------------------------
#define TILE_T 8

__global__ void __launch_bounds__(320) proj_kernel(
    const float* __restrict__ x,
    const float* __restrict__ W_ih0,
    const float* __restrict__ b_ih0,
    const float* __restrict__ b_hh0,
    float* __restrict__ proj)
{
    __shared__ __align__(16) float xs[TILE_T * IN_DIM];

    const int t0 = blockIdx.x * TILE_T;

    const float4* xg  = (const float4*)(x + (size_t)t0 * IN_DIM);
    float4*       xs4 = (float4*)xs;
    for (int i = threadIdx.x; i < TILE_T * (IN_DIM / 4); i += blockDim.x)
        xs4[i] = xg[i];
    __syncthreads();

    const int g  = threadIdx.x % NG;   // gate row 0..79
    const int tg = threadIdx.x / NG;   // 0..3, each handles 2 timesteps

    float acc0 = 0.f, acc1 = 0.f;
    const float4* Wg = (const float4*)(W_ih0 + (size_t)g * IN_DIM);
    const float4* xa = (const float4*)(xs + (tg * 2 + 0) * IN_DIM);
    const float4* xb = (const float4*)(xs + (tg * 2 + 1) * IN_DIM);

    #pragma unroll 8
    for (int k = 0; k < IN_DIM / 4; k++) {
        float4 w = __ldg(&Wg[k]);
        float4 a = xa[k];
        float4 b = xb[k];
        acc0 = fmaf(w.x, a.x, acc0); acc0 = fmaf(w.y, a.y, acc0);
        acc0 = fmaf(w.z, a.z, acc0); acc0 = fmaf(w.w, a.w, acc0);
        acc1 = fmaf(w.x, b.x, acc1); acc1 = fmaf(w.y, b.y, acc1);
        acc1 = fmaf(w.z, b.z, acc1); acc1 = fmaf(w.w, b.w, acc1);
    }

    const float bias = b_ih0[g] + b_hh0[g];
    const int   unit = g % HSZ;
    const int   cls  = g / HSZ;
    const float sc   = (cls == 2) ? 1.0f : 0.5f;   // pre-scale sigmoid gates
    proj[(size_t)(t0 + tg * 2 + 0) * NG + unit * 4 + cls] = (acc0 + bias) * sc;
    proj[(size_t)(t0 + tg * 2 + 1) * NG + unit * 4 + cls] = (acc1 + bias) * sc;
}

// ---------------------------------------------------------------------------
// Packed f32x2 helpers (FFMA2 — PTX-only on sm_103a)
// ---------------------------------------------------------------------------
__device__ __forceinline__ uint64_t pack2(float lo, float hi) {
    uint64_t r;
    asm("mov.b64 %0, {%1, %2};" : "=l"(r) : "f"(lo), "f"(hi));
    return r;
}
__device__ __forceinline__ void unpack2(uint64_t v, float& lo, float& hi) {
    asm("mov.b64 {%0, %1}, %2;" : "=f"(lo), "=f"(hi) : "l"(v));
}
__device__ __forceinline__ void fma2(uint64_t& d, uint64_t a, uint64_t b) {
    asm("fma.rn.f32x2 %0, %1, %2, %3;" : "=l"(d) : "l"(a), "l"(b), "l"(d));
}
__device__ __forceinline__ float tanh_fast(float x) {
    float y;
    asm("tanh.approx.f32 %0, %1;" : "=f"(y) : "f"(x));
    return y;
}
// sigmoid with PRE-HALVED argument: sig(x) = 0.5*tanh(x/2)+0.5, x/2 given.
__device__ __forceinline__ float sig_half(float xh) {
    return fmaf(0.5f, tanh_fast(xh), 0.5f);
}
// sum of the two packed halves
__device__ __forceinline__ float hsum2(uint64_t v) {
    float lo, hi; unpack2(v, lo, hi); return lo + hi;
}
// compiler-only memory fence (same-warp STS->LDS is HW-ordered in-stream)
__device__ __forceinline__ void cfence() { asm volatile("" ::: "memory"); }

// ---------------------------------------------------------------------------
// Kernel 2: single-CTA block-wavefront LSTM, 256 threads = 8 warps.
//   warp 0..2 : input-term helper for layer wid+1 (weights+bias for i,f,o
//               pre-scaled by 0.5)
//   warp 3    : layer-0 projection stager from gmem (proj pre-scaled)
//   warp 4..7 : recurrence warp for layer wid-4 (whh rows for i,f,o
//               pre-scaled by 0.5). Lane j owns unit j.
// Tick n: rec warp L runs block b = n-1-2L; helper l produces pin for block
// n-2l. ONE __syncthreads per tick. Producers write parity p=n&1, consumers
// read p^1.
// ---------------------------------------------------------------------------
__global__ void __launch_bounds__(256, 1) lstm_seq_kernel(
    const float* __restrict__ W_hh0,
    const float* __restrict__ W_ih_r,
    const float* __restrict__ W_hh_r,
    const float* __restrict__ b_ih_r,
    const float* __restrict__ b_hh_r,
    const float* __restrict__ lin_w,
    const float* __restrict__ lin_b,
    const float* __restrict__ proj,
    float* __restrict__ out)
{
    // h_sh[parity][layer][step][unit]
    __shared__ __align__(16) float h_sh[2][NLAYER][U][HSZ];
    // pin_sh[parity][layer][step][unit][gate]
    __shared__ __align__(16) float pin_sh[2][NLAYER][U][HSZ][4];

    const int tid  = threadIdx.x;
    const int wid  = tid >> 5;
    const int lane = tid & 31;
    const bool own = (lane < HSZ);

    // zero shared h state
    for (int i = tid; i < 2 * NLAYER * U * HSZ; i += blockDim.x)
        ((float*)h_sh)[i] = 0.f;
    __syncthreads();

    if (wid >= 4) {
        // ---------------- recurrence warp, layer L ----------------
        const int L = wid - 4;
        uint64_t whh2[4][10];
        if (own) {
            #pragma unroll
            for (int c = 0; c < 4; c++) {
                const float* row = (L == 0)
                    ? (W_hh0 + (c * HSZ + lane) * HSZ)
                    : (W_hh_r + (L - 1) * NG * HSZ + (c * HSZ + lane) * HSZ);
                const float sc = (c == 2) ? 1.0f : 0.5f;
                #pragma unroll
                for (int q = 0; q < 10; q++)
                    whh2[c][q] = pack2(row[2 * q] * sc, row[2 * q + 1] * sc);
            }
        }
        float c_state = 0.f;

        for (int n = 0; n < NT; n++) {
            const int b = n - 1 - 2 * L;
            if (own && b >= 0 && b < NB) {
                const int p = n & 1;
                const float* pin_src = &pin_sh[p ^ 1][L][0][lane][0];
                float*       hw      = &h_sh[p][L][0][0];
                const float* z_prev  = &h_sh[p ^ 1][L][U - 1][0];

                #pragma unroll
                for (int s = 0; s < U; s++) {
                    const float* zs = (s == 0) ? z_prev : (hw + (s - 1) * HSZ);
                    uint64_t z[10];
                    {
                        const ulonglong2* zp = (const ulonglong2*)zs;
                        #pragma unroll
                        for (int q = 0; q < 5; q++) {
                            ulonglong2 v = zp[q];
                            z[2 * q] = v.x; z[2 * q + 1] = v.y;
                        }
                    }
                    const float4 pv = *(const float4*)(pin_src + s * (HSZ * 4));
                    // two 5-deep partial chains per gate (shorter dep tail)
                    uint64_t a0 = pack2(pv.x, 0.f), e0 = 0ull;
                    uint64_t a1 = pack2(pv.y, 0.f), e1 = 0ull;
                    uint64_t a2 = pack2(pv.z, 0.f), e2 = 0ull;
                    uint64_t a3 = pack2(pv.w, 0.f), e3 = 0ull;
                    #pragma unroll
                    for (int q = 0; q < 5; q++) {
                        fma2(a0, whh2[0][q], z[q]);
                        fma2(a1, whh2[1][q], z[q]);
                        fma2(a2, whh2[2][q], z[q]);
                        fma2(a3, whh2[3][q], z[q]);
                        fma2(e0, whh2[0][q + 5], z[q + 5]);
                        fma2(e1, whh2[1][q + 5], z[q + 5]);
                        fma2(e2, whh2[2][q + 5], z[q + 5]);
                        fma2(e3, whh2[3][q + 5], z[q + 5]);
                    }
                    const float gi = hsum2(a0) + hsum2(e0);   // = i_gate/2
                    const float gf = hsum2(a1) + hsum2(e1);   // = f_gate/2
                    const float gg = hsum2(a2) + hsum2(e2);   // = g_gate
                    const float go = hsum2(a3) + hsum2(e3);   // = o_gate/2

                    const float si = sig_half(gi);
                    const float sf = sig_half(gf);
                    const float tg = tanh_fast(gg);
                    const float so = sig_half(go);
                    c_state = fmaf(sf, c_state, si * tg);
                    hw[s * HSZ + lane] = so * tanh_fast(c_state);
                    cfence();   // same-warp STS->LDS: compiler fence only
                }
            }
            __syncthreads();
        }
    } else if (wid < 3) {
        // ---------------- input-term helper, layer l = wid+1 ----------------
        const int l = wid + 1;            // 1..3
        uint64_t wih2[4][10];
        float4   bias4 = make_float4(0.f, 0.f, 0.f, 0.f);
        if (own) {
            const int lbase = (l - 1) * NG * HSZ;
            #pragma unroll
            for (int c = 0; c < 4; c++) {
                const float* ri = W_ih_r + lbase + (c * HSZ + lane) * HSZ;
                const float sc = (c == 2) ? 1.0f : 0.5f;
                #pragma unroll
                for (int q = 0; q < 10; q++)
                    wih2[c][q] = pack2(ri[2 * q] * sc, ri[2 * q + 1] * sc);
            }
            const int bo = (l - 1) * NG + lane;
            bias4.x = 0.5f * (b_ih_r[bo]           + b_hh_r[bo]);
            bias4.y = 0.5f * (b_ih_r[bo + HSZ]     + b_hh_r[bo + HSZ]);
            bias4.z =         b_ih_r[bo + 2 * HSZ] + b_hh_r[bo + 2 * HSZ];
            bias4.w = 0.5f * (b_ih_r[bo + 3 * HSZ] + b_hh_r[bo + 3 * HSZ]);
        }

        for (int n = 0; n < NT; n++) {
            const int b = n - 2 * l;
            if (own && b >= 0 && b < NB) {
                const int p = n & 1;
                const float* hsrc = &h_sh[p ^ 1][l - 1][0][0];
                float*       pw   = &pin_sh[p][l][0][lane][0];

                #pragma unroll
                for (int s = 0; s < U; s++) {
                    uint64_t z[10];
                    {
                        const ulonglong2* zp =
                            (const ulonglong2*)(hsrc + s * HSZ);
                        #pragma unroll
                        for (int q = 0; q < 5; q++) {
                            ulonglong2 v = zp[q];
                            z[2 * q] = v.x; z[2 * q + 1] = v.y;
                        }
                    }
                    uint64_t a0 = pack2(bias4.x, 0.f);
                    uint64_t a1 = pack2(bias4.y, 0.f);
                    uint64_t a2 = pack2(bias4.z, 0.f);
                    uint64_t a3 = pack2(bias4.w, 0.f);
                    #pragma unroll
                    for (int q = 0; q < 10; q++) {
                        fma2(a0, wih2[0][q], z[q]);
                        fma2(a1, wih2[1][q], z[q]);
                        fma2(a2, wih2[2][q], z[q]);
                        fma2(a3, wih2[3][q], z[q]);
                    }
                    float4 r;
                    r.x = hsum2(a0);
                    r.y = hsum2(a1);
                    r.z = hsum2(a2);
                    r.w = hsum2(a3);
                    *(float4*)(pw + s * (HSZ * 4)) = r;
                }
            }
            __syncthreads();
        }
    } else {
        // ---------------- layer-0 projection stager (warp 3) ----------------
        const float4* proj4 = (const float4*)proj;
        for (int n = 0; n < NT; n++) {
            const int b = n;
            if (own && b < NB) {
                const int p = n & 1;
                float4* pw = (float4*)&pin_sh[p][0][0][lane][0];
                #pragma unroll
                for (int s = 0; s < U; s++)
                    pw[s * HSZ] =
                        __ldg(&proj4[(size_t)(b * U + s) * HSZ + lane]);
            }
            __syncthreads();
        }
    }

    __syncthreads();

    // Final linear + sigmoid on h^{L-1}_{T-1}
    if (tid == 0) {
        const int pLast = (NT - 1) & 1;
        float acc = lin_b[0];
        #pragma unroll
        for (int k = 0; k < HSZ; k++)
            acc = fmaf(h_sh[pLast][NLAYER - 1][U - 1][k], lin_w[k], acc);
        out[0] = 1.0f / (1.0f + __expf(-acc));
    }
}

// ---------------------------------------------------------------------------
// Launch
// ---------------------------------------------------------------------------
extern "C" void kernel_launch(void* const* d_in, const int* in_sizes, int n_in,
                              void* d_out, int out_size)
{
    const float* x      = (const float*)d_in[0];
    const float* W_ih0  = (const float*)d_in[1];
    const float* W_hh0  = (const float*)d_in[2];
    const float* b_ih0  = (const float*)d_in[3];
    const float* b_hh0  = (const float*)d_in[4];
    const float* W_ih_r = (const float*)d_in[5];
    const float* W_hh_r = (const float*)d_in[6];
    const float* b_ih_r = (const float*)d_in[7];
    const float* b_hh_r = (const float*)d_in[8];
    const float* lin_w  = (const float*)d_in[9];
    const float* lin_b  = (const float*)d_in[10];
    float* out = (float*)d_out;

    float* proj;
    cudaGetSymbolAddress((void**)&proj, g_proj);

    proj_kernel<<<T_LEN / TILE_T, 320>>>(x, W_ih0, b_ih0, b_hh0, proj);
    lstm_seq_kernel<<<1, 256>>>(W_hh0, W_ih_r, W_hh_r, b_ih_r, b_hh_r,
                                lin_w, lin_b, proj, out);
}